// round 2
// baseline (speedup 1.0000x reference)
#include <cuda_runtime.h>

// ---- compile-time physical constants (match reference float32 pipeline) ----
#define T_STALL_F   (5.4f * (1.0f/100.0f))                 // 0.054
#define W_FREE_F    (1620.0f * (1.0f/60.0f) * 2.0f * 3.14159265358979323846f)
#define A_CONST     (0.129907f + 0.095724f)                // L_X + L_Y
#define R_CONST     (4.0f * 0.0254f)                       // 0.1016
#define INV_R       (1.0f / R_CONST)
#define MOI_CONST   (6.0f * (12.0f*0.0254f)*(12.0f*0.0254f) / 6.0f)  // 0.09290304
#define C_XY        (INV_R / 6.0f)                         // wheel torque -> linear accel
#define C_W         ((A_CONST * INV_R) / MOI_CONST)        // wheel torque -> angular accel

__device__ __forceinline__ float sgnf(float x) {
    return (float)((x > 0.0f) - (x < 0.0f));
}

// Process one row: in r[6] = {x, y, theta, vx, vy, w}; out o[6].
__device__ __forceinline__ void process_row(const float r[6],
                                            float md0, float md1, float md2, float md3,
                                            float o[6]) {
    const float theta = r[2];
    const float vx = r[3], vy = r[4], w = r[5];

    // MUFU hardware sin/cos: |theta| ~ N(0,1), abs err ~1e-6 << 1e-3 gate
    float s, c;
    __sincosf(theta, &s, &c);

    // a2l = rot(cos(-t), sin(-t)) : lv = [c*vx + s*vy, -s*vx + c*vy, w]
    const float lvx = fmaf(c, vx,  s * vy);
    const float lvy = fmaf(c, vy, -s * vx);

    // wheel_vel = LV2WV @ local_vel ; rows (1,-1,-A),(1,1,A),(1,1,-A),(1,-1,A) / R
    const float wA = w * A_CONST;
    const float wv0 = (lvx - lvy - wA) * INV_R;
    const float wv1 = (lvx + lvy + wA) * INV_R;
    const float wv2 = (lvx + lvy - wA) * INV_R;
    const float wv3 = (lvx - lvy + wA) * INV_R;

    // wheel_torque = T_STALL * (1 - |wv| * isd / W_FREE) * md
    const float isd0 = (sgnf(md0 * wv0) + 1.0f) * 0.5f;
    const float isd1 = (sgnf(md1 * wv1) + 1.0f) * 0.5f;
    const float isd2 = (sgnf(md2 * wv2) + 1.0f) * 0.5f;
    const float isd3 = (sgnf(md3 * wv3) + 1.0f) * 0.5f;

    const float invWF = 1.0f / W_FREE_F;
    const float wt0 = T_STALL_F * (1.0f - fabsf(wv0) * isd0 * invWF) * md0;
    const float wt1 = T_STALL_F * (1.0f - fabsf(wv1) * isd1 * invWF) * md1;
    const float wt2 = T_STALL_F * (1.0f - fabsf(wv2) * isd2 * invWF) * md2;
    const float wt3 = T_STALL_F * (1.0f - fabsf(wv3) * isd3 * invWF) * md3;

    // local_accel = WT2LA @ wheel_torque
    const float lax = (wt0 + wt1 + wt2 + wt3) * C_XY;
    const float lay = (-wt0 + wt1 + wt2 - wt3) * C_XY;
    const float laz = (-wt0 + wt1 - wt2 + wt3) * C_W;

    // l2a = rot(cos t, sin t) : aa = [c*lax - s*lay, s*lax + c*lay, laz]
    const float aax = fmaf(c, lax, -s * lay);
    const float aay = fmaf(s, lax,  c * lay);

    o[0] = vx; o[1] = vy; o[2] = w;
    o[3] = aax; o[4] = aay; o[5] = laz;
}

__global__ void __launch_bounds__(256)
mecanum_kernel(const float4* __restrict__ in4,
               const float*  __restrict__ cd,
               float4* __restrict__ out4,
               int nquads, int batch) {
    const int i = blockIdx.x * blockDim.x + threadIdx.x;

    // motor_duty = CD2MD @ control_duty  (uniform; L2-broadcast loads)
    const float c0 = __ldg(cd + 0), c1 = __ldg(cd + 1), c2 = __ldg(cd + 2);
    const float md0 = c0 - c1 - c2;
    const float md1 = c0 + c1 + c2;
    const float md2 = c0 + c1 - c2;
    const float md3 = c0 - c1 + c2;

    if (i < nquads) {
        // four rows = 96 bytes = 6 x float4, front-batched for MLP
        const long long base = 6LL * i;
        float4 v[6];
        #pragma unroll
        for (int k = 0; k < 6; ++k) v[k] = in4[base + k];

        const float* f = (const float*)v;
        float4 o[6];
        float* of = (float*)o;

        #pragma unroll
        for (int r = 0; r < 4; ++r) {
            float row[6], out[6];
            #pragma unroll
            for (int k = 0; k < 6; ++k) row[k] = f[6 * r + k];
            process_row(row, md0, md1, md2, md3, out);
            #pragma unroll
            for (int k = 0; k < 6; ++k) of[6 * r + k] = out[k];
        }

        #pragma unroll
        for (int k = 0; k < 6; ++k) out4[base + k] = o[k];
    } else if (i == nquads) {
        // tail rows (scalar path) — not hit for BATCH = 4,000,000
        const float* inf = (const float*)in4;
        float* outf = (float*)out4;
        for (long long row = 4LL * nquads; row < batch; ++row) {
            const long long b = row * 6;
            float r[6], o[6];
            #pragma unroll
            for (int k = 0; k < 6; ++k) r[k] = inf[b + k];
            process_row(r, md0, md1, md2, md3, o);
            #pragma unroll
            for (int k = 0; k < 6; ++k) outf[b + k] = o[k];
        }
    }
}

extern "C" void kernel_launch(void* const* d_in, const int* in_sizes, int n_in,
                              void* d_out, int out_size) {
    // inputs: [0] t (1), [1] state (B*6), [2] control_duty (3)
    const float* state = (const float*)d_in[1];
    const float* cd    = (const float*)d_in[2];
    float* out = (float*)d_out;

    const int batch  = in_sizes[1] / 6;
    const int nquads = batch / 4;
    const int nthreads = nquads + ((batch & 3) ? 1 : 0);  // extra thread for tail

    const int block = 256;
    const int grid = (nthreads + block - 1) / block;

    mecanum_kernel<<<grid, block>>>((const float4*)state, cd, (float4*)out,
                                    nquads, batch);
}

// round 3
// speedup vs baseline: 1.4157x; 1.4157x over previous
#include <cuda_runtime.h>

// ---- compile-time physical constants (match reference float32 pipeline) ----
#define T_STALL_F   (5.4f * (1.0f/100.0f))                 // 0.054
#define W_FREE_F    (1620.0f * (1.0f/60.0f) * 2.0f * 3.14159265358979323846f)
#define A_CONST     (0.129907f + 0.095724f)                // L_X + L_Y
#define R_CONST     (4.0f * 0.0254f)                       // 0.1016
#define INV_R       (1.0f / R_CONST)
#define MOI_CONST   (6.0f * (12.0f*0.0254f)*(12.0f*0.0254f) / 6.0f)  // 0.09290304
#define C_XY        (INV_R / 6.0f)                         // wheel torque -> linear accel
#define C_W         ((A_CONST * INV_R) / MOI_CONST)        // wheel torque -> angular accel

__device__ __forceinline__ float sgnf(float x) {
    return (float)((x > 0.0f) - (x < 0.0f));
}

// Process one row: in r[6] = {x, y, theta, vx, vy, w}; out o[6].
__device__ __forceinline__ void process_row(const float r[6],
                                            float md0, float md1, float md2, float md3,
                                            float o[6]) {
    const float theta = r[2];
    const float vx = r[3], vy = r[4], w = r[5];

    // MUFU hardware sin/cos: |theta| ~ N(0,1), abs err ~1e-6 << 1e-3 gate
    float s, c;
    __sincosf(theta, &s, &c);

    // a2l = rot(cos(-t), sin(-t)) : lv = [c*vx + s*vy, -s*vx + c*vy, w]
    const float lvx = fmaf(c, vx,  s * vy);
    const float lvy = fmaf(c, vy, -s * vx);

    // wheel_vel = LV2WV @ local_vel ; rows (1,-1,-A),(1,1,A),(1,1,-A),(1,-1,A) / R
    const float wA = w * A_CONST;
    const float wv0 = (lvx - lvy - wA) * INV_R;
    const float wv1 = (lvx + lvy + wA) * INV_R;
    const float wv2 = (lvx + lvy - wA) * INV_R;
    const float wv3 = (lvx - lvy + wA) * INV_R;

    // wheel_torque = T_STALL * (1 - |wv| * isd / W_FREE) * md
    const float isd0 = (sgnf(md0 * wv0) + 1.0f) * 0.5f;
    const float isd1 = (sgnf(md1 * wv1) + 1.0f) * 0.5f;
    const float isd2 = (sgnf(md2 * wv2) + 1.0f) * 0.5f;
    const float isd3 = (sgnf(md3 * wv3) + 1.0f) * 0.5f;

    const float invWF = 1.0f / W_FREE_F;
    const float wt0 = T_STALL_F * (1.0f - fabsf(wv0) * isd0 * invWF) * md0;
    const float wt1 = T_STALL_F * (1.0f - fabsf(wv1) * isd1 * invWF) * md1;
    const float wt2 = T_STALL_F * (1.0f - fabsf(wv2) * isd2 * invWF) * md2;
    const float wt3 = T_STALL_F * (1.0f - fabsf(wv3) * isd3 * invWF) * md3;

    // local_accel = WT2LA @ wheel_torque
    const float lax = (wt0 + wt1 + wt2 + wt3) * C_XY;
    const float lay = (-wt0 + wt1 + wt2 - wt3) * C_XY;
    const float laz = (-wt0 + wt1 - wt2 + wt3) * C_W;

    // l2a = rot(cos t, sin t) : aa = [c*lax - s*lay, s*lax + c*lay, laz]
    const float aax = fmaf(c, lax, -s * lay);
    const float aay = fmaf(s, lax,  c * lay);

    o[0] = vx; o[1] = vy; o[2] = w;
    o[3] = aax; o[4] = aay; o[5] = laz;
}

__global__ void __launch_bounds__(256)
mecanum_kernel(const float4* __restrict__ in4,
               const float*  __restrict__ cd,
               float4* __restrict__ out4,
               int npairs, int batch) {
    const int i = blockIdx.x * blockDim.x + threadIdx.x;

    // motor_duty = CD2MD @ control_duty  (uniform; L2-broadcast loads)
    const float c0 = __ldg(cd + 0), c1 = __ldg(cd + 1), c2 = __ldg(cd + 2);
    const float md0 = c0 - c1 - c2;
    const float md1 = c0 + c1 + c2;
    const float md2 = c0 + c1 - c2;
    const float md3 = c0 - c1 + c2;

    if (i < npairs) {
        // two rows = 48 bytes = 3 x float4, front-batched
        const float4 v0 = in4[3 * i + 0];
        const float4 v1 = in4[3 * i + 1];
        const float4 v2 = in4[3 * i + 2];

        const float r0[6] = {v0.x, v0.y, v0.z, v0.w, v1.x, v1.y};
        const float r1[6] = {v1.z, v1.w, v2.x, v2.y, v2.z, v2.w};

        float o0[6], o1[6];
        process_row(r0, md0, md1, md2, md3, o0);
        process_row(r1, md0, md1, md2, md3, o1);

        out4[3 * i + 0] = make_float4(o0[0], o0[1], o0[2], o0[3]);
        out4[3 * i + 1] = make_float4(o0[4], o0[5], o1[0], o1[1]);
        out4[3 * i + 2] = make_float4(o1[2], o1[3], o1[4], o1[5]);
    } else if (i == npairs && (batch & 1)) {
        // odd tail row (scalar path) — not hit for BATCH = 4,000,000
        const float* inf = (const float*)in4;
        float* outf = (float*)out4;
        const long long base = (long long)(batch - 1) * 6;
        float r[6], o[6];
        #pragma unroll
        for (int k = 0; k < 6; ++k) r[k] = inf[base + k];
        process_row(r, md0, md1, md2, md3, o);
        #pragma unroll
        for (int k = 0; k < 6; ++k) outf[base + k] = o[k];
    }
}

extern "C" void kernel_launch(void* const* d_in, const int* in_sizes, int n_in,
                              void* d_out, int out_size) {
    // inputs: [0] t (1), [1] state (B*6), [2] control_duty (3)
    const float* state = (const float*)d_in[1];
    const float* cd    = (const float*)d_in[2];
    float* out = (float*)d_out;

    const int batch  = in_sizes[1] / 6;
    const int npairs = batch / 2;
    const int nthreads = npairs + (batch & 1);   // extra thread for odd tail

    const int block = 256;
    const int grid = (nthreads + block - 1) / block;

    mecanum_kernel<<<grid, block>>>((const float4*)state, cd, (float4*)out,
                                    npairs, batch);
}

// round 4
// speedup vs baseline: 1.4453x; 1.0209x over previous
#include <cuda_runtime.h>

// ---- compile-time physical constants (match reference float32 pipeline) ----
#define T_STALL_F   (5.4f * (1.0f/100.0f))                 // 0.054
#define W_FREE_F    (1620.0f * (1.0f/60.0f) * 2.0f * 3.14159265358979323846f)
#define A_CONST     (0.129907f + 0.095724f)                // L_X + L_Y
#define R_CONST     (4.0f * 0.0254f)                       // 0.1016
#define INV_R       (1.0f / R_CONST)
#define MOI_CONST   (6.0f * (12.0f*0.0254f)*(12.0f*0.0254f) / 6.0f)  // 0.09290304
#define C_XY        (INV_R / 6.0f)                         // wheel torque -> linear accel
#define C_W         ((A_CONST * INV_R) / MOI_CONST)        // wheel torque -> angular accel

#define BLOCK 256
#define ROWS_PER_BLOCK (2 * BLOCK)            // 512 rows
#define F4_PER_BLOCK   (ROWS_PER_BLOCK * 6 / 4)  // 768 float4

__device__ __forceinline__ float sgnf(float x) {
    return (float)((x > 0.0f) - (x < 0.0f));
}

// Process one row: in r[6] = {x, y, theta, vx, vy, w}; out o[6].
__device__ __forceinline__ void process_row(const float r[6],
                                            float md0, float md1, float md2, float md3,
                                            float o[6]) {
    const float theta = r[2];
    const float vx = r[3], vy = r[4], w = r[5];

    // MUFU hardware sin/cos: |theta| ~ N(0,1), abs err ~1e-6 << 1e-3 gate
    float s, c;
    __sincosf(theta, &s, &c);

    const float lvx = fmaf(c, vx,  s * vy);
    const float lvy = fmaf(c, vy, -s * vx);

    const float wA = w * A_CONST;
    const float wv0 = (lvx - lvy - wA) * INV_R;
    const float wv1 = (lvx + lvy + wA) * INV_R;
    const float wv2 = (lvx + lvy - wA) * INV_R;
    const float wv3 = (lvx - lvy + wA) * INV_R;

    const float isd0 = (sgnf(md0 * wv0) + 1.0f) * 0.5f;
    const float isd1 = (sgnf(md1 * wv1) + 1.0f) * 0.5f;
    const float isd2 = (sgnf(md2 * wv2) + 1.0f) * 0.5f;
    const float isd3 = (sgnf(md3 * wv3) + 1.0f) * 0.5f;

    const float invWF = 1.0f / W_FREE_F;
    const float wt0 = T_STALL_F * (1.0f - fabsf(wv0) * isd0 * invWF) * md0;
    const float wt1 = T_STALL_F * (1.0f - fabsf(wv1) * isd1 * invWF) * md1;
    const float wt2 = T_STALL_F * (1.0f - fabsf(wv2) * isd2 * invWF) * md2;
    const float wt3 = T_STALL_F * (1.0f - fabsf(wv3) * isd3 * invWF) * md3;

    const float lax = (wt0 + wt1 + wt2 + wt3) * C_XY;
    const float lay = (-wt0 + wt1 + wt2 - wt3) * C_XY;
    const float laz = (-wt0 + wt1 - wt2 + wt3) * C_W;

    const float aax = fmaf(c, lax, -s * lay);
    const float aay = fmaf(s, lax,  c * lay);

    o[0] = vx; o[1] = vy; o[2] = w;
    o[3] = aax; o[4] = aay; o[5] = laz;
}

__global__ void __launch_bounds__(BLOCK)
mecanum_kernel(const float4* __restrict__ in4,
               const float*  __restrict__ cd,
               float4* __restrict__ out4,
               int nfull, int batch) {
    __shared__ float4 s4[F4_PER_BLOCK];   // 12 KB

    const int bid = blockIdx.x;
    const int t = threadIdx.x;

    // motor_duty = CD2MD @ control_duty  (uniform; L2-broadcast loads)
    const float c0 = __ldg(cd + 0), c1 = __ldg(cd + 1), c2 = __ldg(cd + 2);
    const float md0 = c0 - c1 - c2;
    const float md1 = c0 + c1 + c2;
    const float md2 = c0 + c1 - c2;
    const float md3 = c0 - c1 + c2;

    if (bid < nfull) {
        const long long f4base = (long long)F4_PER_BLOCK * bid;

        // 1) fully coalesced global loads -> smem
        #pragma unroll
        for (int k = 0; k < 3; ++k)
            s4[t + BLOCK * k] = in4[f4base + t + BLOCK * k];
        __syncthreads();

        // 2) each thread: 2 rows = 12 contiguous floats = 3 LDS.128 at word 12t
        //    (conflict-free across quad-phases)
        float4 a = s4[3 * t + 0];
        float4 b = s4[3 * t + 1];
        float4 d = s4[3 * t + 2];

        const float r0[6] = {a.x, a.y, a.z, a.w, b.x, b.y};
        const float r1[6] = {b.z, b.w, d.x, d.y, d.z, d.w};

        float o0[6], o1[6];
        process_row(r0, md0, md1, md2, md3, o0);
        process_row(r1, md0, md1, md2, md3, o1);

        // 3) write back to the SAME smem words this thread read (no hazard)
        s4[3 * t + 0] = make_float4(o0[0], o0[1], o0[2], o0[3]);
        s4[3 * t + 1] = make_float4(o0[4], o0[5], o1[0], o1[1]);
        s4[3 * t + 2] = make_float4(o1[2], o1[3], o1[4], o1[5]);
        __syncthreads();

        // 4) fully coalesced global stores
        #pragma unroll
        for (int k = 0; k < 3; ++k)
            out4[f4base + t + BLOCK * k] = s4[t + BLOCK * k];
    } else {
        // tail block: scalar per-row path for rows [nfull*512, batch)
        const float* inf = (const float*)in4;
        float* outf = (float*)out4;
        for (long long row = (long long)nfull * ROWS_PER_BLOCK + t;
             row < batch; row += BLOCK) {
            const long long base = row * 6;
            float r[6], o[6];
            #pragma unroll
            for (int k = 0; k < 6; ++k) r[k] = inf[base + k];
            process_row(r, md0, md1, md2, md3, o);
            #pragma unroll
            for (int k = 0; k < 6; ++k) outf[base + k] = o[k];
        }
    }
}

extern "C" void kernel_launch(void* const* d_in, const int* in_sizes, int n_in,
                              void* d_out, int out_size) {
    // inputs: [0] t (1), [1] state (B*6), [2] control_duty (3)
    const float* state = (const float*)d_in[1];
    const float* cd    = (const float*)d_in[2];
    float* out = (float*)d_out;

    const int batch = in_sizes[1] / 6;
    const int nfull = batch / ROWS_PER_BLOCK;                 // full blocks
    const int tail  = batch - nfull * ROWS_PER_BLOCK;
    const int grid  = nfull + (tail ? 1 : 0);

    mecanum_kernel<<<grid, BLOCK>>>((const float4*)state, cd, (float4*)out,
                                    nfull, batch);
}